// round 4
// baseline (speedup 1.0000x reference)
#include <cuda_runtime.h>

#define HW (768*768)

// XLA algebraic-simplifier semantics: x / const -> x * (1/const)
#define C3  (1.0f / 3.0f)
#define C81 (1.0f / 81.0f)

// packed f32x2 add: two independent round-to-nearest fp32 adds (bit-exact per lane)
__device__ __forceinline__ unsigned long long addx2(unsigned long long a, unsigned long long b) {
    unsigned long long r;
    asm("add.rn.f32x2 %0, %1, %2;" : "=l"(r) : "l"(a), "l"(b));
    return r;
}

// smem layout (bytes):
//   P2 : [0, 42624)      72 rows x 74 float2 (pxx,pyy), XOR-swizzled at 16B grain
//   P1 : [42624, 64512)  72 rows x 76 float  (pxy)
//   M  : [64512, 88192)  74 rows x 80 float  (channel mean, zero-padded halo)
#define P2_OFF 0
#define P1_OFF 42624
#define M_OFF  64512
#define SMEM_BYTES 88192

// bank-conflict swizzle for P2: fold addr bit7 into bit4 (16B-chunk granularity,
// preserves 16B alignment; same formula on store and load)
__device__ __forceinline__ unsigned swz(unsigned off) {
    return off ^ ((off >> 3) & 0x10u);
}

// Update one product row pr into the accumulators of output rows [LO..HI].
// Per output the add order is exactly reduce_window's flat row-major sequence:
// rows ascending (caller), columns c=0..8 ascending (here).
template<int LO, int HI>
__device__ __forceinline__ void row_update(
    const char* __restrict__ P2b, const float* __restrict__ P1,
    int pr, int oc,
    unsigned long long (&a2)[4][4], float (&axy)[4][4])
{
    unsigned long long w2[12];
    unsigned base2 = (unsigned)((pr * 74 + oc) * 8);
    #pragma unroll
    for (int k = 0; k < 6; k++) {
        unsigned off = swz(base2 + (unsigned)(k * 16));
        ulonglong2 q = *(const ulonglong2*)(P2b + off);
        w2[2 * k] = q.x; w2[2 * k + 1] = q.y;
    }
    float w1[12];
    const float4* p1r = (const float4*)&P1[pr * 76 + oc];
    float4 f0 = p1r[0], f1 = p1r[1], f2 = p1r[2];
    w1[0] = f0.x; w1[1] = f0.y; w1[2]  = f0.z; w1[3]  = f0.w;
    w1[4] = f1.x; w1[5] = f1.y; w1[6]  = f1.z; w1[7]  = f1.w;
    w1[8] = f2.x; w1[9] = f2.y; w1[10] = f2.z; w1[11] = f2.w;

    #pragma unroll
    for (int oi = LO; oi <= HI; oi++) {
        #pragma unroll
        for (int cc = 0; cc < 4; cc++) {
            #pragma unroll
            for (int c = 0; c < 9; c++) {
                a2[oi][cc] = addx2(a2[oi][cc], w2[cc + c]);
                axy[oi][cc] = __fadd_rn(axy[oi][cc], w1[cc + c]);
            }
        }
    }
}

__global__ void __launch_bounds__(256, 2) k_fused(const float* __restrict__ x,
                                                  float* __restrict__ out) {
    extern __shared__ char smem[];
    char*  P2b = smem + P2_OFF;
    float* P1  = (float*)(smem + P1_OFF);
    float* M   = (float*)(smem + M_OFF);

    const int j0 = blockIdx.x * 64;
    const int i0 = blockIdx.y * 64;
    const int b  = blockIdx.z;
    const int t  = threadIdx.x;
    const float* xb = x + (size_t)b * 3 * HW;

    // ---- Phase A: M[74][80] = channel mean; M row 0 = src row i0-5,
    //      M col 0 = src col j0-8 (float4 aligned). OOB -> 0 (pad semantics).
    for (int s = t; s < 74 * 20; s += 256) {
        int mr = s / 20, k = s - mr * 20;
        int gr = i0 - 5 + mr;
        int gc = j0 - 8 + 4 * k;
        float4 v = make_float4(0.f, 0.f, 0.f, 0.f);
        if ((unsigned)gr < 768u && (unsigned)gc <= 764u) {
            size_t off = (size_t)gr * 768 + gc;
            float4 a  = *(const float4*)(xb + off);
            float4 c1 = *(const float4*)(xb + HW + off);
            float4 c2 = *(const float4*)(xb + 2 * HW + off);
            v.x = __fmul_rn(__fadd_rn(__fadd_rn(a.x, c1.x), c2.x), C3);
            v.y = __fmul_rn(__fadd_rn(__fadd_rn(a.y, c1.y), c2.y), C3);
            v.z = __fmul_rn(__fadd_rn(__fadd_rn(a.z, c1.z), c2.z), C3);
            v.w = __fmul_rn(__fadd_rn(__fadd_rn(a.w, c1.w), c2.w), C3);
        }
        *(float4*)&M[mr * 80 + 4 * k] = v;
    }
    __syncthreads();

    // ---- Phase B: Sobel (exact reference op order) + products.
    //      P row pr = src row i0-4+pr, P col pc = src col j0-4+pc; OOB -> 0.
    for (int s = t; s < 72 * 72; s += 256) {
        int pr = s / 72, pc = s - pr * 72;
        int sr = i0 - 4 + pr, sc = j0 - 4 + pc;
        float pxx = 0.f, pyy = 0.f, pxy = 0.f;
        if ((unsigned)sr < 768u && (unsigned)sc < 768u) {
            int mr = pr + 1, mc = pc + 4;
            const float* r0p = &M[(mr - 1) * 80 + mc];
            const float* r1p = &M[ mr      * 80 + mc];
            const float* r2p = &M[(mr + 1) * 80 + mc];
            float m00 = r0p[-1], m01 = r0p[0], m02 = r0p[1];
            float m10 = r1p[-1],               m12 = r1p[1];
            float m20 = r2p[-1], m21 = r2p[0], m22 = r2p[1];

            float rlx_u = __fsub_rn(m02, m00);
            float rlx_c = __fsub_rn(m12, m10);
            float rlx_d = __fsub_rn(m22, m20);
            float tx3 = __fadd_rn(__fadd_rn(rlx_u, rlx_c), rlx_d);
            float sxv = __fadd_rn(rlx_c, __fmul_rn(__fmul_rn(tx3, C3), 3.f));

            float btx_l = __fsub_rn(m20, m00);
            float btx_c = __fsub_rn(m21, m01);
            float btx_r = __fsub_rn(m22, m02);
            float ty3 = __fadd_rn(__fadd_rn(btx_l, btx_c), btx_r);
            float syv = __fadd_rn(btx_c, __fmul_rn(__fmul_rn(ty3, C3), 3.f));

            pxx = __fmul_rn(sxv, sxv);
            pyy = __fmul_rn(syv, syv);
            pxy = __fmul_rn(sxv, syv);
        }
        unsigned off = swz((unsigned)((pr * 74 + pc) * 8));
        *(float2*)(P2b + off) = make_float2(pxx, pyy);
        P1[pr * 76 + pc] = pxy;
    }
    __syncthreads();

    // ---- Phase C: per-thread 4x4 output block; 12-row sweep with register reuse.
    const int ui = t >> 4, uj = t & 15;
    const int orow = ui * 4;        // local output row base
    const int oc   = uj * 4;        // local output col base

    unsigned long long a2[4][4];
    float axy[4][4];
    #pragma unroll
    for (int oi = 0; oi < 4; oi++)
        #pragma unroll
        for (int cc = 0; cc < 4; cc++) { a2[oi][cc] = 0ull; axy[oi][cc] = 0.f; }

    row_update<0, 0>(P2b, P1, orow + 0,  oc, a2, axy);
    row_update<0, 1>(P2b, P1, orow + 1,  oc, a2, axy);
    row_update<0, 2>(P2b, P1, orow + 2,  oc, a2, axy);
    #pragma unroll 1
    for (int rr = 3; rr <= 8; rr++)
        row_update<0, 3>(P2b, P1, orow + rr, oc, a2, axy);
    row_update<1, 3>(P2b, P1, orow + 9,  oc, a2, axy);
    row_update<2, 3>(P2b, P1, orow + 10, oc, a2, axy);
    row_update<3, 3>(P2b, P1, orow + 11, oc, a2, axy);

    // ---- eigen-direction math (strict rn, identical to R3) + store
    float* ob = out + (size_t)b * 3 * HW;
    #pragma unroll
    for (int oi = 0; oi < 4; oi++) {
        float ex4[4], ey4[4];
        #pragma unroll
        for (int cc = 0; cc < 4; cc++) {
            unsigned long long v = a2[oi][cc];
            float xx = __fmul_rn(__uint_as_float((unsigned)v), C81);
            float yy = __fmul_rn(__uint_as_float((unsigned)(v >> 32)), C81);
            float xy = __fmul_rn(axy[oi][cc], C81);
            float bq = -__fadd_rn(xx, yy);
            float cq = __fsub_rn(__fmul_rn(xx, yy), __fmul_rn(xy, xy));
            float disc = __fsub_rn(__fmul_rn(bq, bq), __fmul_rn(4.f, cq));
            disc = fmaxf(disc, 0.f);
            float deta = __fsqrt_rn(disc);
            float l1 = __fmul_rn(__fadd_rn(-bq, deta), 0.5f);
            float yd = __fsub_rn(xx, l1);
            float s2 = __fadd_rn(__fadd_rn(__fmul_rn(xy, xy), __fmul_rn(yd, yd)), 1e-8f);
            float l  = __fadd_rn(__fsqrt_rn(s2), 1e-8f);
            ex4[cc] = __fdiv_rn(xy, l);
            ey4[cc] = __fdiv_rn(yd, l);
        }
        size_t o = (size_t)(i0 + orow + oi) * 768 + (j0 + oc);
        *(float4*)&ob[o]          = make_float4(ex4[0], ex4[1], ex4[2], ex4[3]);
        *(float4*)&ob[o + HW]     = make_float4(ey4[0], ey4[1], ey4[2], ey4[3]);
        *(float4*)&ob[o + 2*HW]   = make_float4(ex4[0], ex4[1], ex4[2], ex4[3]);
    }
}

extern "C" void kernel_launch(void* const* d_in, const int* in_sizes, int n_in,
                              void* d_out, int out_size) {
    const float* x = (const float*)d_in[0];
    float* out = (float*)d_out;

    cudaFuncSetAttribute(k_fused, cudaFuncAttributeMaxDynamicSharedMemorySize, SMEM_BYTES);
    dim3 grid(768 / 64, 768 / 64, 32);   // (12, 12, 32)
    k_fused<<<grid, 256, SMEM_BYTES>>>(x, out);
}

// round 5
// speedup vs baseline: 1.0601x; 1.0601x over previous
#include <cuda_runtime.h>

#define HW (768*768)
#define NB 32

// XLA algebraic-simplifier semantics: x / const -> x * (1/const)
#define C3  (1.0f / 3.0f)
#define C81 (1.0f / 81.0f)

// scratch: interleaved (sx, sy) per pixel
__device__ __align__(16) float2 g_s[(size_t)NB * HW];

// packed f32x2 add: two independent round-to-nearest fp32 adds (bit-exact per lane)
__device__ __forceinline__ unsigned long long addx2(unsigned long long a, unsigned long long b) {
    unsigned long long r;
    asm("add.rn.f32x2 %0, %1, %2;" : "=l"(r) : "l"(a), "l"(b));
    return r;
}

// bank-conflict swizzle for P2: fold addr bit7 into bit4 (16B granularity,
// preserves 16B alignment; identical formula on store and load)
__device__ __forceinline__ unsigned swz(unsigned off) {
    return off ^ ((off >> 3) & 0x10u);
}

// ---------------------------------------------------------------------------
// Kernel 1: M = channel mean (zero-padded) via sum*(1/3), Sobel with exact
// reference op order. Identical to the bit-exact R3 version.
// ---------------------------------------------------------------------------
__global__ void __launch_bounds__(256) k_sobel(const float* __restrict__ x) {
    __shared__ float M[34 * 72];

    const int col0 = blockIdx.x * 64;
    const int row0 = blockIdx.y * 32;
    const int b    = blockIdx.z;
    const int t    = threadIdx.x;
    const float* xb = x + (size_t)b * 3 * HW;

    for (int s = t; s < 34 * 18; s += 256) {
        int rr = s / 18, k = s - rr * 18;
        int gr = row0 - 1 + rr;
        int gc = col0 - 4 + 4 * k;
        float4 v = make_float4(0.f, 0.f, 0.f, 0.f);
        if ((unsigned)gr < 768u && (unsigned)gc <= 764u) {
            size_t off = (size_t)gr * 768 + gc;
            float4 a  = *(const float4*)(xb + off);
            float4 c1 = *(const float4*)(xb + HW + off);
            float4 c2 = *(const float4*)(xb + 2 * HW + off);
            v.x = __fmul_rn(__fadd_rn(__fadd_rn(a.x, c1.x), c2.x), C3);
            v.y = __fmul_rn(__fadd_rn(__fadd_rn(a.y, c1.y), c2.y), C3);
            v.z = __fmul_rn(__fadd_rn(__fadd_rn(a.z, c1.z), c2.z), C3);
            v.w = __fmul_rn(__fadd_rn(__fadd_rn(a.w, c1.w), c2.w), C3);
        }
        *(float4*)&M[rr * 72 + 4 * k] = v;
    }
    __syncthreads();

    const int c  = t & 63;
    const int rg = t >> 6;
    const int sc = c + 4;
    float2* sb = g_s + (size_t)b * HW;

    #pragma unroll
    for (int i = 0; i < 8; i++) {
        int rl = rg * 8 + i;
        int sr = rl + 1;
        const float* r0p = &M[(sr - 1) * 72 + sc];
        const float* r1p = &M[ sr      * 72 + sc];
        const float* r2p = &M[(sr + 1) * 72 + sc];
        float m00 = r0p[-1], m01 = r0p[0], m02 = r0p[1];
        float m10 = r1p[-1],               m12 = r1p[1];
        float m20 = r2p[-1], m21 = r2p[0], m22 = r2p[1];

        float rlx_u = __fsub_rn(m02, m00);
        float rlx_c = __fsub_rn(m12, m10);
        float rlx_d = __fsub_rn(m22, m20);
        float tx3 = __fadd_rn(__fadd_rn(rlx_u, rlx_c), rlx_d);
        float sxv = __fadd_rn(rlx_c, __fmul_rn(__fmul_rn(tx3, C3), 3.f));

        float btx_l = __fsub_rn(m20, m00);
        float btx_c = __fsub_rn(m21, m01);
        float btx_r = __fsub_rn(m22, m02);
        float ty3 = __fadd_rn(__fadd_rn(btx_l, btx_c), btx_r);
        float syv = __fadd_rn(btx_c, __fmul_rn(__fmul_rn(ty3, C3), 3.f));

        sb[(size_t)(row0 + rl) * 768 + col0 + c] = make_float2(sxv, syv);
    }
}

// ---------------------------------------------------------------------------
// k_struct row update: one product row pr into output rows [LO..HI] of this
// thread's 2x4 block. Exact reduce_window flat row-major order per output:
// caller sweeps rows ascending; columns c=0..8 ascending here. xx,yy packed.
// ---------------------------------------------------------------------------
template<int LO, int HI>
__device__ __forceinline__ void row_update(
    const char* __restrict__ P2b, const float* __restrict__ P1,
    int pr, int oc,
    unsigned long long (&a2)[2][4], float (&axy)[2][4])
{
    unsigned long long w2[12];
    unsigned base2 = (unsigned)((pr * 74 + oc) * 8);
    #pragma unroll
    for (int k = 0; k < 6; k++) {
        unsigned off = swz(base2 + (unsigned)(k * 16));
        ulonglong2 q = *(const ulonglong2*)(P2b + off);
        w2[2 * k] = q.x; w2[2 * k + 1] = q.y;
    }
    float w1[12];
    const float4* p1r = (const float4*)&P1[pr * 76 + oc];
    float4 f0 = p1r[0], f1 = p1r[1], f2 = p1r[2];
    w1[0] = f0.x; w1[1] = f0.y; w1[2]  = f0.z; w1[3]  = f0.w;
    w1[4] = f1.x; w1[5] = f1.y; w1[6]  = f1.z; w1[7]  = f1.w;
    w1[8] = f2.x; w1[9] = f2.y; w1[10] = f2.z; w1[11] = f2.w;

    #pragma unroll
    for (int oi = LO; oi <= HI; oi++) {
        #pragma unroll
        for (int cc = 0; cc < 4; cc++) {
            #pragma unroll
            for (int c = 0; c < 9; c++) {
                a2[oi][cc] = addx2(a2[oi][cc], w2[cc + c]);
                axy[oi][cc] = __fadd_rn(axy[oi][cc], w1[cc + c]);
            }
        }
    }
}

// ---------------------------------------------------------------------------
// Kernel 2: 9x9 box sums (exact order) + eigen math. 64x32 tile, 256 threads,
// 4 cols x 2 rows per thread. xx,yy interleaved float2 (packed adds).
// ---------------------------------------------------------------------------
__global__ void __launch_bounds__(256, 4) k_struct(float* __restrict__ out) {
    __shared__ __align__(16) char  P2b[40 * 74 * 8];  // (pxx,pyy) swizzled
    __shared__ float P1[40 * 76];                      // pxy

    const int col0 = blockIdx.x * 64;
    const int row0 = blockIdx.y * 32;
    const int b    = blockIdx.z;
    const int t    = threadIdx.x;
    const float2* sb = g_s + (size_t)b * HW;

    // load halo (rows row0-4..row0+35, cols col0-4..col0+67) as float4
    // (= 2 float2), compute products, store
    for (int s = t; s < 40 * 36; s += 256) {
        int rr = s / 36, k = s - rr * 36;
        int gr = row0 - 4 + rr;
        int g  = col0 - 4 + 2 * k;
        float4 v = make_float4(0.f, 0.f, 0.f, 0.f);
        if ((unsigned)gr < 768u && (unsigned)g <= 766u) {
            v = *(const float4*)&sb[(size_t)gr * 768 + g];
        }
        int pc = 2 * k;
        unsigned off = swz((unsigned)((rr * 74 + pc) * 8));
        // two adjacent float2 slots; swizzle is 16B-granular so the pair stays together
        *(float4*)(P2b + off) = make_float4(__fmul_rn(v.x, v.x), __fmul_rn(v.y, v.y),
                                            __fmul_rn(v.z, v.z), __fmul_rn(v.w, v.w));
        P1[rr * 76 + pc]     = __fmul_rn(v.x, v.y);
        P1[rr * 76 + pc + 1] = __fmul_rn(v.z, v.w);
    }
    __syncthreads();

    const int uj = t & 15, ui = t >> 4;
    const int oc   = uj * 4;       // local output col base
    const int orow = ui * 2;       // local output row base

    unsigned long long a2[2][4];
    float axy[2][4];
    #pragma unroll
    for (int oi = 0; oi < 2; oi++)
        #pragma unroll
        for (int cc = 0; cc < 4; cc++) { a2[oi][cc] = 0ull; axy[oi][cc] = 0.f; }

    row_update<0, 0>(P2b, P1, orow + 0, oc, a2, axy);
    row_update<0, 1>(P2b, P1, orow + 1, oc, a2, axy);
    row_update<0, 1>(P2b, P1, orow + 2, oc, a2, axy);
    row_update<0, 1>(P2b, P1, orow + 3, oc, a2, axy);
    row_update<0, 1>(P2b, P1, orow + 4, oc, a2, axy);
    row_update<0, 1>(P2b, P1, orow + 5, oc, a2, axy);
    row_update<0, 1>(P2b, P1, orow + 6, oc, a2, axy);
    row_update<0, 1>(P2b, P1, orow + 7, oc, a2, axy);
    row_update<0, 1>(P2b, P1, orow + 8, oc, a2, axy);
    row_update<1, 1>(P2b, P1, orow + 9, oc, a2, axy);

    // eigen-direction math (strict rn, identical to R3/R4) + store
    float* ob = out + (size_t)b * 3 * HW;
    #pragma unroll
    for (int oi = 0; oi < 2; oi++) {
        float ex4[4], ey4[4];
        #pragma unroll
        for (int cc = 0; cc < 4; cc++) {
            unsigned long long v = a2[oi][cc];
            float xx = __fmul_rn(__uint_as_float((unsigned)v), C81);
            float yy = __fmul_rn(__uint_as_float((unsigned)(v >> 32)), C81);
            float xy = __fmul_rn(axy[oi][cc], C81);
            float bq = -__fadd_rn(xx, yy);
            float cq = __fsub_rn(__fmul_rn(xx, yy), __fmul_rn(xy, xy));
            float disc = __fsub_rn(__fmul_rn(bq, bq), __fmul_rn(4.f, cq));
            disc = fmaxf(disc, 0.f);
            float deta = __fsqrt_rn(disc);
            float l1 = __fmul_rn(__fadd_rn(-bq, deta), 0.5f);
            float yd = __fsub_rn(xx, l1);
            float s2 = __fadd_rn(__fadd_rn(__fmul_rn(xy, xy), __fmul_rn(yd, yd)), 1e-8f);
            float l  = __fadd_rn(__fsqrt_rn(s2), 1e-8f);
            ex4[cc] = __fdiv_rn(xy, l);
            ey4[cc] = __fdiv_rn(yd, l);
        }
        size_t o = (size_t)(row0 + orow + oi) * 768 + (col0 + oc);
        *(float4*)&ob[o]          = make_float4(ex4[0], ex4[1], ex4[2], ex4[3]);
        *(float4*)&ob[o + HW]     = make_float4(ey4[0], ey4[1], ey4[2], ey4[3]);
        *(float4*)&ob[o + 2*HW]   = make_float4(ex4[0], ex4[1], ex4[2], ex4[3]);
    }
}

extern "C" void kernel_launch(void* const* d_in, const int* in_sizes, int n_in,
                              void* d_out, int out_size) {
    const float* x = (const float*)d_in[0];
    float* out = (float*)d_out;

    dim3 grid(768 / 64, 768 / 32, NB);   // (12, 24, 32)
    k_sobel<<<grid, 256>>>(x);
    k_struct<<<grid, 256>>>(out);
}

// round 6
// speedup vs baseline: 1.0957x; 1.0335x over previous
#include <cuda_runtime.h>

#define HW (768*768)

// XLA algebraic-simplifier semantics: x / const -> x * (1/const)
#define C3  (1.0f / 3.0f)
#define C81 (1.0f / 81.0f)

// packed f32x2 add: two independent rn fp32 adds (bit-exact per lane)
__device__ __forceinline__ unsigned long long addx2(unsigned long long a, unsigned long long b) {
    unsigned long long r;
    asm("add.rn.f32x2 %0, %1, %2;" : "=l"(r) : "l"(a), "l"(b));
    return r;
}
// packed operand builders (pure asm -> CSE-able)
__device__ __forceinline__ unsigned long long dup2(float w) {
    unsigned long long r; asm("mov.b64 %0, {%1, %1};" : "=l"(r) : "f"(w)); return r;
}
__device__ __forceinline__ unsigned long long lo0(float w) {   // (w, +0)
    unsigned long long r; asm("mov.b64 %0, {%1, %2};" : "=l"(r) : "f"(w), "f"(0.0f)); return r;
}
__device__ __forceinline__ unsigned long long hi0(float w) {   // (+0, w)
    unsigned long long r; asm("mov.b64 %0, {%1, %2};" : "=l"(r) : "f"(0.0f), "f"(w)); return r;
}

// bank-conflict swizzle for P2 (16B granularity, same formula store & load)
__device__ __forceinline__ unsigned swz(unsigned off) {
    return off ^ ((off >> 3) & 0x10u);
}

// dynamic smem layout (bytes)
#define P2_OFF 0                       // 40 x 74 float2 (pxx,pyy) swizzled : 23680
#define P1_OFF 23680                   // 40 x 76 float (pxy)              : 12160
#define M_OFF  35840                   // 42 x 80 float (channel mean)     : 13440
#define SMEM_BYTES 49280

// one product row pr -> this thread's accumulators.
// MODE 0: first row (only output row 0's window); 1: middle (both);
// 2: last row (only output row 1). xy packed across the two output rows:
// lane0 = row0, lane1 = row1. Per-lane add order = reduce_window flat
// row-major (rows ascending via caller, cols c=0..8 ascending here).
template<int MODE>
__device__ __forceinline__ void row_update(
    const char* __restrict__ P2b, const float* __restrict__ P1,
    int pr, int oc,
    unsigned long long (&a2)[2][4], unsigned long long (&axy2)[4])
{
    unsigned long long w2[12];
    unsigned base2 = (unsigned)((pr * 74 + oc) * 8);
    #pragma unroll
    for (int k = 0; k < 6; k++) {
        unsigned off = swz(base2 + (unsigned)(k * 16));
        ulonglong2 q = *(const ulonglong2*)(P2b + off);
        w2[2 * k] = q.x; w2[2 * k + 1] = q.y;
    }
    float w1[12];
    const float4* p1r = (const float4*)&P1[pr * 76 + oc];
    float4 f0 = p1r[0], f1 = p1r[1], f2 = p1r[2];
    w1[0] = f0.x; w1[1] = f0.y; w1[2]  = f0.z; w1[3]  = f0.w;
    w1[4] = f1.x; w1[5] = f1.y; w1[6]  = f1.z; w1[7]  = f1.w;
    w1[8] = f2.x; w1[9] = f2.y; w1[10] = f2.z; w1[11] = f2.w;

    #pragma unroll
    for (int cc = 0; cc < 4; cc++) {
        #pragma unroll
        for (int c = 0; c < 9; c++) {
            if (MODE != 2) a2[0][cc] = addx2(a2[0][cc], w2[cc + c]);
            if (MODE != 0) a2[1][cc] = addx2(a2[1][cc], w2[cc + c]);
            unsigned long long wd = (MODE == 0) ? lo0(w1[cc + c])
                                  : (MODE == 2) ? hi0(w1[cc + c])
                                                : dup2(w1[cc + c]);
            axy2[cc] = addx2(axy2[cc], wd);
        }
    }
}

__global__ void __launch_bounds__(256, 4) k_fused(const float* __restrict__ x,
                                                  float* __restrict__ out) {
    extern __shared__ char smem[];
    char*  P2b = smem + P2_OFF;
    float* P1  = (float*)(smem + P1_OFF);
    float* M   = (float*)(smem + M_OFF);

    const int col0 = blockIdx.x * 64;
    const int row0 = blockIdx.y * 32;
    const int b    = blockIdx.z;
    const int t    = threadIdx.x;
    const float* xb = x + (size_t)b * 3 * HW;

    // ---- Phase A: M[42][80] = channel mean; M[0][0] <-> src (row0-5, col0-8).
    for (int s = t; s < 42 * 20; s += 256) {
        int mr = s / 20, k = s - mr * 20;
        int gr = row0 - 5 + mr;
        int gc = col0 - 8 + 4 * k;
        float4 v = make_float4(0.f, 0.f, 0.f, 0.f);
        if ((unsigned)gr < 768u && (unsigned)gc <= 764u) {
            size_t off = (size_t)gr * 768 + gc;
            float4 a  = *(const float4*)(xb + off);
            float4 c1 = *(const float4*)(xb + HW + off);
            float4 c2 = *(const float4*)(xb + 2 * HW + off);
            v.x = __fmul_rn(__fadd_rn(__fadd_rn(a.x, c1.x), c2.x), C3);
            v.y = __fmul_rn(__fadd_rn(__fadd_rn(a.y, c1.y), c2.y), C3);
            v.z = __fmul_rn(__fadd_rn(__fadd_rn(a.z, c1.z), c2.z), C3);
            v.w = __fmul_rn(__fadd_rn(__fadd_rn(a.w, c1.w), c2.w), C3);
        }
        *(float4*)&M[mr * 80 + 4 * k] = v;
    }
    __syncthreads();

    // ---- Phase B: Sobel (exact reference op order) + products into P2/P1.
    //      P(pr,pc) <-> src (row0-4+pr, col0-4+pc); OOB -> 0.
    for (int s = t; s < 40 * 72; s += 256) {
        int pr = s / 72, pc = s - pr * 72;
        int sr = row0 - 4 + pr, sc = col0 - 4 + pc;
        float pxx = 0.f, pyy = 0.f, pxy = 0.f;
        if ((unsigned)sr < 768u && (unsigned)sc < 768u) {
            int mr = pr + 1, mc = pc + 4;
            const float* r0p = &M[(mr - 1) * 80 + mc];
            const float* r1p = &M[ mr      * 80 + mc];
            const float* r2p = &M[(mr + 1) * 80 + mc];
            float m00 = r0p[-1], m01 = r0p[0], m02 = r0p[1];
            float m10 = r1p[-1],               m12 = r1p[1];
            float m20 = r2p[-1], m21 = r2p[0], m22 = r2p[1];

            float rlx_u = __fsub_rn(m02, m00);
            float rlx_c = __fsub_rn(m12, m10);
            float rlx_d = __fsub_rn(m22, m20);
            float tx3 = __fadd_rn(__fadd_rn(rlx_u, rlx_c), rlx_d);
            float sxv = __fadd_rn(rlx_c, __fmul_rn(__fmul_rn(tx3, C3), 3.f));

            float btx_l = __fsub_rn(m20, m00);
            float btx_c = __fsub_rn(m21, m01);
            float btx_r = __fsub_rn(m22, m02);
            float ty3 = __fadd_rn(__fadd_rn(btx_l, btx_c), btx_r);
            float syv = __fadd_rn(btx_c, __fmul_rn(__fmul_rn(ty3, C3), 3.f));

            pxx = __fmul_rn(sxv, sxv);
            pyy = __fmul_rn(syv, syv);
            pxy = __fmul_rn(sxv, syv);
        }
        unsigned off = swz((unsigned)((pr * 74 + pc) * 8));
        *(float2*)(P2b + off) = make_float2(pxx, pyy);
        P1[pr * 76 + pc] = pxy;
    }
    __syncthreads();

    // ---- Phase C: 2 rows x 4 cols per thread; 10-row sweep.
    const int uj = t & 15, ui = t >> 4;
    const int oc   = uj * 4;
    const int orow = ui * 2;

    unsigned long long a2[2][4];
    unsigned long long axy2[4];
    #pragma unroll
    for (int cc = 0; cc < 4; cc++) { a2[0][cc] = 0ull; a2[1][cc] = 0ull; axy2[cc] = 0ull; }

    row_update<0>(P2b, P1, orow + 0, oc, a2, axy2);
    row_update<1>(P2b, P1, orow + 1, oc, a2, axy2);
    row_update<1>(P2b, P1, orow + 2, oc, a2, axy2);
    row_update<1>(P2b, P1, orow + 3, oc, a2, axy2);
    row_update<1>(P2b, P1, orow + 4, oc, a2, axy2);
    row_update<1>(P2b, P1, orow + 5, oc, a2, axy2);
    row_update<1>(P2b, P1, orow + 6, oc, a2, axy2);
    row_update<1>(P2b, P1, orow + 7, oc, a2, axy2);
    row_update<1>(P2b, P1, orow + 8, oc, a2, axy2);
    row_update<2>(P2b, P1, orow + 9, oc, a2, axy2);

    // ---- eigen-direction math (strict rn, identical to R3-R5) + store
    float* ob = out + (size_t)b * 3 * HW;
    #pragma unroll
    for (int oi = 0; oi < 2; oi++) {
        float ex4[4], ey4[4];
        #pragma unroll
        for (int cc = 0; cc < 4; cc++) {
            unsigned long long v = a2[oi][cc];
            float xx = __fmul_rn(__uint_as_float((unsigned)v), C81);
            float yy = __fmul_rn(__uint_as_float((unsigned)(v >> 32)), C81);
            unsigned long long vq = axy2[cc];
            float xyr = (oi == 0) ? __uint_as_float((unsigned)vq)
                                  : __uint_as_float((unsigned)(vq >> 32));
            float xy = __fmul_rn(xyr, C81);
            float bq = -__fadd_rn(xx, yy);
            float cq = __fsub_rn(__fmul_rn(xx, yy), __fmul_rn(xy, xy));
            float disc = __fsub_rn(__fmul_rn(bq, bq), __fmul_rn(4.f, cq));
            disc = fmaxf(disc, 0.f);
            float deta = __fsqrt_rn(disc);
            float l1 = __fmul_rn(__fadd_rn(-bq, deta), 0.5f);
            float yd = __fsub_rn(xx, l1);
            float s2 = __fadd_rn(__fadd_rn(__fmul_rn(xy, xy), __fmul_rn(yd, yd)), 1e-8f);
            float l  = __fadd_rn(__fsqrt_rn(s2), 1e-8f);
            ex4[cc] = __fdiv_rn(xy, l);
            ey4[cc] = __fdiv_rn(yd, l);
        }
        size_t o = (size_t)(row0 + orow + oi) * 768 + (col0 + oc);
        *(float4*)&ob[o]          = make_float4(ex4[0], ex4[1], ex4[2], ex4[3]);
        *(float4*)&ob[o + HW]     = make_float4(ey4[0], ey4[1], ey4[2], ey4[3]);
        *(float4*)&ob[o + 2*HW]   = make_float4(ex4[0], ex4[1], ex4[2], ex4[3]);
    }
}

extern "C" void kernel_launch(void* const* d_in, const int* in_sizes, int n_in,
                              void* d_out, int out_size) {
    const float* x = (const float*)d_in[0];
    float* out = (float*)d_out;

    cudaFuncSetAttribute(k_fused, cudaFuncAttributeMaxDynamicSharedMemorySize, SMEM_BYTES);
    dim3 grid(768 / 64, 768 / 32, 32);   // (12, 24, 32)
    k_fused<<<grid, 256, SMEM_BYTES>>>(x, out);
}